// round 3
// baseline (speedup 1.0000x reference)
#include <cuda_runtime.h>
#include <math.h>
#include <float.h>

// Problem shape (fixed by the reference)
constexpr int B_ = 2;
constexpr int C_ = 16;
constexpr int D_ = 80;
constexpr int H_ = 96;
constexpr int W_ = 96;
constexpr int DHW = D_ * H_ * W_;             // 737280
constexpr int SP  = B_ * DHW;                 // 1474560
constexpr size_t TEN = (size_t)B_ * C_ * DHW; // elements per tensor

// Scratch: pooled fields [pmax_fix, pavg_fix, pmax_move, pavg_move]
__device__ float g_pool[4 * SP];

typedef unsigned long long ull;

__device__ __forceinline__ ull pack2(float lo, float hi) {
    ull r;
    asm("mov.b64 %0, {%1, %2};" : "=l"(r) : "f"(lo), "f"(hi));
    return r;
}
__device__ __forceinline__ void unpack2(float& lo, float& hi, ull v) {
    asm("mov.b64 {%0, %1}, %2;" : "=f"(lo), "=f"(hi) : "l"(v));
}
// packed dual-fp32 FMA: d = a*b + d  (FFMA2 on sm_103a)
__device__ __forceinline__ void fma2(ull& d, ull a, ull b) {
    asm("fma.rn.f32x2 %0, %1, %2, %0;" : "+l"(d) : "l"(a), "l"(b));
}

// ---------------------------------------------------------------------------
// Kernel 1: channel max/avg pooling for both tensors (float4 vectorized)
// ---------------------------------------------------------------------------
__global__ __launch_bounds__(256)
void pool_kernel(const float* __restrict__ fix, const float* __restrict__ mov) {
    int g4 = blockIdx.x * blockDim.x + threadIdx.x;   // index over float4 sites
    constexpr int Q = DHW / 4;
    if (g4 >= SP / 4) return;
    int b  = g4 / Q;
    int s4 = g4 - b * Q;

    const float4* pf = reinterpret_cast<const float4*>(fix) + (size_t)b * C_ * Q + s4;
    const float4* pm = reinterpret_cast<const float4*>(mov) + (size_t)b * C_ * Q + s4;

    float4 mxf = make_float4(-FLT_MAX, -FLT_MAX, -FLT_MAX, -FLT_MAX);
    float4 mxm = mxf;
    float4 smf = make_float4(0.f, 0.f, 0.f, 0.f);
    float4 smm = smf;
#pragma unroll
    for (int c = 0; c < C_; c++) {
        float4 v = pf[(size_t)c * Q];
        mxf.x = fmaxf(mxf.x, v.x); mxf.y = fmaxf(mxf.y, v.y);
        mxf.z = fmaxf(mxf.z, v.z); mxf.w = fmaxf(mxf.w, v.w);
        smf.x += v.x; smf.y += v.y; smf.z += v.z; smf.w += v.w;
        float4 u = pm[(size_t)c * Q];
        mxm.x = fmaxf(mxm.x, u.x); mxm.y = fmaxf(mxm.y, u.y);
        mxm.z = fmaxf(mxm.z, u.z); mxm.w = fmaxf(mxm.w, u.w);
        smm.x += u.x; smm.y += u.y; smm.z += u.z; smm.w += u.w;
    }
    const float inv = 1.f / 16.f;
    smf.x *= inv; smf.y *= inv; smf.z *= inv; smf.w *= inv;
    smm.x *= inv; smm.y *= inv; smm.z *= inv; smm.w *= inv;

    float4* gp = reinterpret_cast<float4*>(g_pool);
    constexpr int SP4 = SP / 4;
    gp[0 * SP4 + g4] = mxf;
    gp[1 * SP4 + g4] = smf;
    gp[2 * SP4 + g4] = mxm;
    gp[3 * SP4 + g4] = smm;
}

// ---------------------------------------------------------------------------
// Kernel 2: 7x7x7 conv (2ch, 2 gates) + sigmoid + cross-gated residual
// Tile: 32(W) x 32(H) x 2(D), 128 threads (8,8,2), per-thread 4W x 4H outputs
// H dimension packed pairwise into fma.rn.f32x2
// ---------------------------------------------------------------------------
constexpr int TW = 32, TH = 32, TD = 2;
constexpr int HX = TW + 6;   // 38
constexpr int HXS = 40;      // padded row stride (16B alignment)
constexpr int HY = TH + 6;   // 38
constexpr int HZ = TD + 6;   // 8
constexpr int HALO_F = HZ * HY * HXS;              // 12160 floats
constexpr int SMEM_BYTES = HALO_F * 4 + 343 * 8;   // halo + duplicated weights

__global__ void __launch_bounds__(128, 4)
conv_apply_kernel(const float* __restrict__ fix, const float* __restrict__ mov,
                  const float* __restrict__ w_f2m, const float* __restrict__ w_m2f,
                  float* __restrict__ out) {
    extern __shared__ float smem[];
    float* s_h  = smem;                              // [HZ][HY][HXS]
    ull*   s_w2 = reinterpret_cast<ull*>(smem + HALO_F);  // 343 dup-pairs

    const int tx = threadIdx.x;   // 0..7  (4 W outputs each)
    const int ty = threadIdx.y;   // 0..7  (4 H outputs each)
    const int tz = threadIdx.z;   // 0..1
    const int tid = tx + ty * 8 + tz * 64;

    const int x0 = blockIdx.x * TW;
    const int y0 = blockIdx.y * TH;
    const int bz = blockIdx.z;                // 0..79
    const int b  = bz / (D_ / TD);
    const int z0 = (bz - b * (D_ / TD)) * TD;

    // acc[gate][w][hpair] ; hpair packs outputs h=2*hp (lo), 2*hp+1 (hi)
    ull acc[2][4][2];
#pragma unroll
    for (int g = 0; g < 2; g++)
#pragma unroll
        for (int w = 0; w < 4; w++)
#pragma unroll
            for (int p = 0; p < 2; p++) acc[g][w][p] = 0ull;

#pragma unroll 1
    for (int gc = 0; gc < 4; gc++) {         // field = gc ; gate = gc>>1 ; ch = gc&1
        const int g = gc >> 1;
        // ---- halo for this pooled field ----
        const float* src = g_pool + (size_t)gc * SP + (size_t)b * DHW;
        for (int i = tid; i < HZ * HY * HX; i += 128) {
            int dz  = i / (HY * HX);
            int rem = i - dz * (HY * HX);
            int dy  = rem / HX;
            int dx  = rem - dy * HX;
            int gz = z0 + dz - 3, gy = y0 + dy - 3, gx = x0 + dx - 3;
            float v = 0.f;
            if (gz >= 0 && gz < D_ && gy >= 0 && gy < H_ && gx >= 0 && gx < W_)
                v = src[(gz * H_ + gy) * W_ + gx];
            s_h[(dz * HY + dy) * HXS + dx] = v;
        }
        // ---- duplicated weight pairs for this (gate, channel) ----
        const float* wsrc = (g == 0 ? w_f2m : w_m2f) + (gc & 1) * 343;
        for (int i = tid; i < 343; i += 128) {
            float wv = wsrc[i];
            s_w2[i] = pack2(wv, wv);
        }
        __syncthreads();

        // ---- conv accumulate ----
#pragma unroll 1
        for (int kz = 0; kz < 7; kz++) {
            const float* slab = s_h + ((tz + kz) * HY + ty * 4) * HXS + tx * 4;
            const ull*   wz   = s_w2 + kz * 49;

            float rb[2][10];
            {
                float4 a = *reinterpret_cast<const float4*>(slab);
                float4 c4 = *reinterpret_cast<const float4*>(slab + 4);
                float2 e = *reinterpret_cast<const float2*>(slab + 8);
                rb[0][0]=a.x; rb[0][1]=a.y; rb[0][2]=a.z; rb[0][3]=a.w;
                rb[0][4]=c4.x; rb[0][5]=c4.y; rb[0][6]=c4.z; rb[0][7]=c4.w;
                rb[0][8]=e.x; rb[0][9]=e.y;
            }
#pragma unroll
            for (int r = 0; r < 9; r++) {
                float* cur = rb[r & 1];
                float* nxt = rb[(r + 1) & 1];
                {
                    const float* p = slab + (r + 1) * HXS;
                    float4 a = *reinterpret_cast<const float4*>(p);
                    float4 c4 = *reinterpret_cast<const float4*>(p + 4);
                    float2 e = *reinterpret_cast<const float2*>(p + 8);
                    nxt[0]=a.x; nxt[1]=a.y; nxt[2]=a.z; nxt[3]=a.w;
                    nxt[4]=c4.x; nxt[5]=c4.y; nxt[6]=c4.z; nxt[7]=c4.w;
                    nxt[8]=e.x; nxt[9]=e.y;
                }
                ull pk[10];
#pragma unroll
                for (int x = 0; x < 10; x++) pk[x] = pack2(cur[x], nxt[x]);

                if (r <= 6) {            // hpair 0: outputs h=0,1 use ky=r
#pragma unroll
                    for (int kx = 0; kx < 7; kx++) {
                        ull wp = wz[r * 7 + kx];
#pragma unroll
                        for (int w = 0; w < 4; w++)
                            fma2(acc[g][w][0], pk[kx + w], wp);
                    }
                }
                if (r >= 2) {            // hpair 1: outputs h=2,3 use ky=r-2
#pragma unroll
                    for (int kx = 0; kx < 7; kx++) {
                        ull wp = wz[(r - 2) * 7 + kx];
#pragma unroll
                        for (int w = 0; w < 4; w++)
                            fma2(acc[g][w][1], pk[kx + w], wp);
                    }
                }
            }
        }
        __syncthreads();   // protect smem before next field overwrites
    }

    // ---- sigmoid gates:  gate[g][w][h] ----
    float gate[2][4][4];
#pragma unroll
    for (int g = 0; g < 2; g++)
#pragma unroll
        for (int w = 0; w < 4; w++)
#pragma unroll
            for (int p = 0; p < 2; p++) {
                float lo, hi;
                unpack2(lo, hi, acc[g][w][p]);
                gate[g][w][2 * p + 0] = 1.f / (1.f + __expf(-lo));
                gate[g][w][2 * p + 1] = 1.f / (1.f + __expf(-hi));
            }

    // ---- apply: fix_out = mov*sa_fix + fix ; move_out = fix*sa_move + mov ----
    const int z = z0 + tz;
    const int yb = y0 + ty * 4;
    const int x = x0 + tx * 4;
    const size_t sbase = (size_t)b * C_ * DHW + (size_t)z * H_ * W_ + (size_t)yb * W_ + x;
    float* out_f = out;
    float* out_m = out + TEN;

#pragma unroll 1
    for (int c = 0; c < C_; c++) {
        size_t oc = sbase + (size_t)c * DHW;
#pragma unroll
        for (int h = 0; h < 4; h++) {
            size_t o = oc + (size_t)h * W_;
            float4 f = *reinterpret_cast<const float4*>(fix + o);
            float4 m = *reinterpret_cast<const float4*>(mov + o);
            float4 of, om;
            of.x = fmaf(m.x, gate[0][0][h], f.x);  om.x = fmaf(f.x, gate[1][0][h], m.x);
            of.y = fmaf(m.y, gate[0][1][h], f.y);  om.y = fmaf(f.y, gate[1][1][h], m.y);
            of.z = fmaf(m.z, gate[0][2][h], f.z);  om.z = fmaf(f.z, gate[1][2][h], m.z);
            of.w = fmaf(m.w, gate[0][3][h], f.w);  om.w = fmaf(f.w, gate[1][3][h], m.w);
            *reinterpret_cast<float4*>(out_f + o) = of;
            *reinterpret_cast<float4*>(out_m + o) = om;
        }
    }
}

// ---------------------------------------------------------------------------
extern "C" void kernel_launch(void* const* d_in, const int* in_sizes, int n_in,
                              void* d_out, int out_size) {
    const float* fix   = (const float*)d_in[0];
    const float* mov   = (const float*)d_in[1];
    const float* w_f2m = (const float*)d_in[2];
    const float* w_m2f = (const float*)d_in[3];
    float* out = (float*)d_out;

    static bool attr_set = false;
    if (!attr_set) {
        cudaFuncSetAttribute(conv_apply_kernel,
                             cudaFuncAttributeMaxDynamicSharedMemorySize, SMEM_BYTES);
        attr_set = true;
    }

    // Pass 1: pooling
    {
        int threads = 256;
        int blocks = (SP / 4 + threads - 1) / threads;   // 1440
        pool_kernel<<<blocks, threads>>>(fix, mov);
    }
    // Pass 2: conv + sigmoid + gated residual
    {
        dim3 block(8, 8, 2);
        dim3 grid(W_ / TW, H_ / TH, B_ * (D_ / TD));     // 3 x 3 x 80
        conv_apply_kernel<<<grid, block, SMEM_BYTES>>>(fix, mov, w_f2m, w_m2f, out);
    }
}

// round 4
// speedup vs baseline: 1.1849x; 1.1849x over previous
#include <cuda_runtime.h>
#include <math.h>
#include <float.h>

// Problem shape (fixed by the reference)
constexpr int B_ = 2;
constexpr int C_ = 16;
constexpr int D_ = 80;
constexpr int H_ = 96;
constexpr int W_ = 96;
constexpr int DHW = D_ * H_ * W_;             // 737280
constexpr int SP  = B_ * DHW;                 // 1474560
constexpr size_t TEN = (size_t)B_ * C_ * DHW; // elements per tensor

// Scratch: pooled fields [pmax_fix, pavg_fix, pmax_move, pavg_move]
__device__ float g_pool[4 * SP];

// ---------------------------------------------------------------------------
// Kernel 1: channel max/avg pooling for both tensors (float4 vectorized)
// ---------------------------------------------------------------------------
__global__ __launch_bounds__(256)
void pool_kernel(const float* __restrict__ fix, const float* __restrict__ mov) {
    int g4 = blockIdx.x * blockDim.x + threadIdx.x;
    constexpr int Q = DHW / 4;
    if (g4 >= SP / 4) return;
    int b  = g4 / Q;
    int s4 = g4 - b * Q;

    const float4* pf = reinterpret_cast<const float4*>(fix) + (size_t)b * C_ * Q + s4;
    const float4* pm = reinterpret_cast<const float4*>(mov) + (size_t)b * C_ * Q + s4;

    float4 mxf = make_float4(-FLT_MAX, -FLT_MAX, -FLT_MAX, -FLT_MAX);
    float4 mxm = mxf;
    float4 smf = make_float4(0.f, 0.f, 0.f, 0.f);
    float4 smm = smf;
#pragma unroll
    for (int c = 0; c < C_; c++) {
        float4 v = pf[(size_t)c * Q];
        mxf.x = fmaxf(mxf.x, v.x); mxf.y = fmaxf(mxf.y, v.y);
        mxf.z = fmaxf(mxf.z, v.z); mxf.w = fmaxf(mxf.w, v.w);
        smf.x += v.x; smf.y += v.y; smf.z += v.z; smf.w += v.w;
        float4 u = pm[(size_t)c * Q];
        mxm.x = fmaxf(mxm.x, u.x); mxm.y = fmaxf(mxm.y, u.y);
        mxm.z = fmaxf(mxm.z, u.z); mxm.w = fmaxf(mxm.w, u.w);
        smm.x += u.x; smm.y += u.y; smm.z += u.z; smm.w += u.w;
    }
    const float inv = 1.f / 16.f;
    smf.x *= inv; smf.y *= inv; smf.z *= inv; smf.w *= inv;
    smm.x *= inv; smm.y *= inv; smm.z *= inv; smm.w *= inv;

    float4* gp = reinterpret_cast<float4*>(g_pool);
    constexpr int SP4 = SP / 4;
    gp[0 * SP4 + g4] = mxf;
    gp[1 * SP4 + g4] = smf;
    gp[2 * SP4 + g4] = mxm;
    gp[3 * SP4 + g4] = smm;
}

// ---------------------------------------------------------------------------
// Kernel 2: 7x7x7 conv (2ch, 2 gates) + sigmoid + cross-gated residual
// Tile: 32(W) x 32(H) x 2(D), 128 threads (8,8,2), per-thread 4W x 4H outputs
// Scalar FFMA (no packing). One pooled field in smem at a time.
// ---------------------------------------------------------------------------
constexpr int TW = 32, TH = 32, TD = 2;
constexpr int HX = TW + 6;   // 38
constexpr int HXS = 40;      // padded row stride (16B alignment)
constexpr int HY = TH + 6;   // 38
constexpr int HZ = TD + 6;   // 8
constexpr int HALO_F = HZ * HY * HXS;              // 12160 floats = 48.64 KB
constexpr int SMEM_BYTES = (HALO_F + 343) * 4;

__global__ void __launch_bounds__(128, 4)
conv_apply_kernel(const float* __restrict__ fix, const float* __restrict__ mov,
                  const float* __restrict__ w_f2m, const float* __restrict__ w_m2f,
                  float* __restrict__ out) {
    extern __shared__ float smem[];
    float* s_h = smem;             // [HZ][HY][HXS]
    float* s_w = smem + HALO_F;    // 343 weights of current field

    const int tx = threadIdx.x;    // 0..7  (4 W outputs each)
    const int ty = threadIdx.y;    // 0..7  (4 H outputs each)
    const int tz = threadIdx.z;    // 0..1
    const int tid = tx + ty * 8 + tz * 64;

    const int x0 = blockIdx.x * TW;
    const int y0 = blockIdx.y * TH;
    const int bz = blockIdx.z;
    const int b  = bz / (D_ / TD);
    const int z0 = (bz - b * (D_ / TD)) * TD;

    float acc0[4][4], acc1[4][4];     // [w][h] for gate0, gate1
#pragma unroll
    for (int w = 0; w < 4; w++)
#pragma unroll
        for (int h = 0; h < 4; h++) { acc0[w][h] = 0.f; acc1[w][h] = 0.f; }

#pragma unroll 1
    for (int gc = 0; gc < 4; gc++) {   // field: gate = gc>>1, channel = gc&1
        const bool gate0 = (gc < 2);

        // ---- halo for this pooled field ----
        const float* src = g_pool + (size_t)gc * SP + (size_t)b * DHW;
        for (int i = tid; i < HZ * HY * HX; i += 128) {
            int dz  = i / (HY * HX);
            int rem = i - dz * (HY * HX);
            int dy  = rem / HX;
            int dx  = rem - dy * HX;
            int gz = z0 + dz - 3, gy = y0 + dy - 3, gx = x0 + dx - 3;
            float v = 0.f;
            if (gz >= 0 && gz < D_ && gy >= 0 && gy < H_ && gx >= 0 && gx < W_)
                v = src[(gz * H_ + gy) * W_ + gx];
            s_h[(dz * HY + dy) * HXS + dx] = v;
        }
        // ---- weights of this (gate, channel) ----
        const float* wsrc = (gate0 ? w_f2m : w_m2f) + (gc & 1) * 343;
        for (int i = tid; i < 343; i += 128) s_w[i] = wsrc[i];
        __syncthreads();

        // ---- conv into tmp (static register indices) ----
        float tmp[4][4];
#pragma unroll
        for (int w = 0; w < 4; w++)
#pragma unroll
            for (int h = 0; h < 4; h++) tmp[w][h] = 0.f;

#pragma unroll 1
        for (int kz = 0; kz < 7; kz++) {
            const float* slab = s_h + ((tz + kz) * HY + ty * 4) * HXS + tx * 4;
            const float* wz   = s_w + kz * 49;
#pragma unroll
            for (int r = 0; r < 10; r++) {
                const float* p = slab + r * HXS;
                float4 a  = *reinterpret_cast<const float4*>(p);
                float4 c4 = *reinterpret_cast<const float4*>(p + 4);
                float2 e  = *reinterpret_cast<const float2*>(p + 8);
                float rv[10] = {a.x, a.y, a.z, a.w,
                                c4.x, c4.y, c4.z, c4.w,
                                e.x, e.y};
#pragma unroll
                for (int h = 0; h < 4; h++) {
                    const int ky = r - h;
                    if (ky >= 0 && ky <= 6) {
#pragma unroll
                        for (int kx = 0; kx < 7; kx++) {
                            float wv = wz[ky * 7 + kx];
#pragma unroll
                            for (int w = 0; w < 4; w++)
                                tmp[w][h] = fmaf(rv[kx + w], wv, tmp[w][h]);
                        }
                    }
                }
            }
        }

        // ---- merge tmp into the right gate accumulator (predicated) ----
#pragma unroll
        for (int w = 0; w < 4; w++)
#pragma unroll
            for (int h = 0; h < 4; h++) {
                if (gate0) acc0[w][h] += tmp[w][h];
                else       acc1[w][h] += tmp[w][h];
            }

        __syncthreads();   // protect smem before next field overwrites
    }

    // ---- sigmoid gates ----
    float gf[4][4], gm[4][4];
#pragma unroll
    for (int w = 0; w < 4; w++)
#pragma unroll
        for (int h = 0; h < 4; h++) {
            gf[w][h] = 1.f / (1.f + __expf(-acc0[w][h]));
            gm[w][h] = 1.f / (1.f + __expf(-acc1[w][h]));
        }

    // ---- apply: fix_out = mov*sa_fix + fix ; move_out = fix*sa_move + mov ----
    const int z  = z0 + tz;
    const int yb = y0 + ty * 4;
    const int x  = x0 + tx * 4;
    const size_t sbase = (size_t)b * C_ * DHW + (size_t)z * H_ * W_ + (size_t)yb * W_ + x;
    float* out_f = out;
    float* out_m = out + TEN;

#pragma unroll 1
    for (int c = 0; c < C_; c++) {
        size_t oc = sbase + (size_t)c * DHW;
#pragma unroll
        for (int h = 0; h < 4; h++) {
            size_t o = oc + (size_t)h * W_;
            float4 f = *reinterpret_cast<const float4*>(fix + o);
            float4 m = *reinterpret_cast<const float4*>(mov + o);
            float4 of, om;
            of.x = fmaf(m.x, gf[0][h], f.x);  om.x = fmaf(f.x, gm[0][h], m.x);
            of.y = fmaf(m.y, gf[1][h], f.y);  om.y = fmaf(f.y, gm[1][h], m.y);
            of.z = fmaf(m.z, gf[2][h], f.z);  om.z = fmaf(f.z, gm[2][h], m.z);
            of.w = fmaf(m.w, gf[3][h], f.w);  om.w = fmaf(f.w, gm[3][h], m.w);
            *reinterpret_cast<float4*>(out_f + o) = of;
            *reinterpret_cast<float4*>(out_m + o) = om;
        }
    }
}

// ---------------------------------------------------------------------------
extern "C" void kernel_launch(void* const* d_in, const int* in_sizes, int n_in,
                              void* d_out, int out_size) {
    const float* fix   = (const float*)d_in[0];
    const float* mov   = (const float*)d_in[1];
    const float* w_f2m = (const float*)d_in[2];
    const float* w_m2f = (const float*)d_in[3];
    float* out = (float*)d_out;

    static bool attr_set = false;
    if (!attr_set) {
        cudaFuncSetAttribute(conv_apply_kernel,
                             cudaFuncAttributeMaxDynamicSharedMemorySize, SMEM_BYTES);
        attr_set = true;
    }

    // Pass 1: pooling
    {
        int threads = 256;
        int blocks = (SP / 4 + threads - 1) / threads;
        pool_kernel<<<blocks, threads>>>(fix, mov);
    }
    // Pass 2: conv + sigmoid + gated residual
    {
        dim3 block(8, 8, 2);
        dim3 grid(W_ / TW, H_ / TH, B_ * (D_ / TD));  // 3 x 3 x 80
        conv_apply_kernel<<<grid, block, SMEM_BYTES>>>(fix, mov, w_f2m, w_m2f, out);
    }
}